// round 8
// baseline (speedup 1.0000x reference)
#include <cuda_runtime.h>
#include <cuda_bf16.h>
#include <cstdint>

#define BT_   8192
#define IN_   4096
#define OUT_  4096
#define R_    64
#define T_    8

// ---------------- device scratch ----------------
__device__ float          g_W1[T_ * R_ * R_];
__device__ __nv_bfloat16  g_Bthi[T_ * R_ * IN_];   // Bt = in_core@W1 : [t][n][k]
__device__ __nv_bfloat16  g_Btlo[T_ * R_ * IN_];
__device__ __nv_bfloat16  g_ochi[OUT_ * R_];       // out_core [n][k]
__device__ __nv_bfloat16  g_oclo[OUT_ * R_];

typedef unsigned long long u64;

// ---------- packed f32x2 (k_bt only) ----------
__device__ __forceinline__ u64 pk2(float lo, float hi) {
    u64 r; asm("mov.b64 %0, {%1, %2};" : "=l"(r) : "f"(lo), "f"(hi)); return r;
}
__device__ __forceinline__ void upk2(u64 v, float& lo, float& hi) {
    asm("mov.b64 {%0, %1}, %2;" : "=f"(lo), "=f"(hi) : "l"(v));
}
__device__ __forceinline__ u64 ffma2(u64 a, u64 b, u64 c) {
    u64 d; asm("fma.rn.f32x2 %0, %1, %2, %3;" : "=l"(d) : "l"(a), "l"(b), "l"(c)); return d;
}

// ---------- fp32 -> bf16 hi/lo split ----------
__device__ __forceinline__ void split2(float a, float b, uint32_t& h, uint32_t& l) {
    __nv_bfloat162 hh = __floats2bfloat162_rn(a, b);
    float ra = a - __bfloat162float(hh.x);
    float rb = b - __bfloat162float(hh.y);
    __nv_bfloat162 ll = __floats2bfloat162_rn(ra, rb);
    h = *(uint32_t*)&hh; l = *(uint32_t*)&ll;
}
__device__ __forceinline__ void split4(float4 v, uint32_t& h01, uint32_t& h23,
                                       uint32_t& l01, uint32_t& l23) {
    split2(v.x, v.y, h01, l01);
    split2(v.z, v.w, h23, l23);
}

// ---------- tensor-core primitives (base-ISA, sm_103-safe) ----------
__device__ __forceinline__ void mma16816(float* c, uint32_t a0, uint32_t a1,
                                         uint32_t a2, uint32_t a3,
                                         uint32_t b0, uint32_t b1) {
    asm volatile(
        "mma.sync.aligned.m16n8k16.row.col.f32.bf16.bf16.f32 "
        "{%0,%1,%2,%3}, {%4,%5,%6,%7}, {%8,%9}, {%0,%1,%2,%3};"
        : "+f"(c[0]), "+f"(c[1]), "+f"(c[2]), "+f"(c[3])
        : "r"(a0), "r"(a1), "r"(a2), "r"(a3), "r"(b0), "r"(b1));
}
__device__ __forceinline__ void ldsm4(uint32_t* r, uint32_t saddr) {
    asm volatile("ldmatrix.sync.aligned.m8n8.x4.shared.b16 {%0,%1,%2,%3}, [%4];"
                 : "=r"(r[0]), "=r"(r[1]), "=r"(r[2]), "=r"(r[3]) : "r"(saddr));
}
__device__ __forceinline__ void cpa16(uint32_t dst, const void* src) {
    asm volatile("cp.async.cg.shared.global [%0], [%1], 16;" :: "r"(dst), "l"(src));
}
#define CP_COMMIT() asm volatile("cp.async.commit_group;" ::: "memory")
#define CP_WAIT0()  asm volatile("cp.async.wait_group 0;" ::: "memory")

__device__ __forceinline__ uint32_t smem_u32(const void* p) {
    uint32_t a;
    asm("{ .reg .u64 t; cvta.to.shared.u64 t, %1; cvt.u32.u64 %0, t; }" : "=r"(a) : "l"(p));
    return a;
}

#define RSTR 144   // smem row stride (bytes): conflict-free LDSM

// smem map for fused kernel:
//   phase1 B stages: [0, 18432) and [18432, 36864)   (BH@+0, BL@+9216)
//   phase2 B stages: [0, 73728) and [73728, 147456)  (BH@+0, BL@+36864)
//   v tile:          VHI@147456, VLO@156672          (64 x RSTR each)
#define P1_STG   18432
#define P2_STG   73728
#define VHI      147456
#define VLO      156672
#define FU_SMEM  165888

// ---------------------------------------------------------------------------
// k_pre1: out_core hi/lo split (bx<64) + W1 (bx in [64,192)).
// ---------------------------------------------------------------------------
__global__ __launch_bounds__(256) void k_pre1(const float* __restrict__ task,
                                              const float* __restrict__ tc,
                                              const float* __restrict__ out_core) {
    const int bx = blockIdx.x, tid = threadIdx.x;
    if (bx < 64) {
        const size_t base = (size_t)bx * 4096 + (size_t)tid * 16;
#pragma unroll
        for (int j = 0; j < 16; j += 4) {
            float4 v = *(const float4*)&out_core[base + j];
            uint32_t h01, h23, l01, l23;
            split4(v, h01, h23, l01, l23);
            *(uint32_t*)&g_ochi[base + j]     = h01;
            *(uint32_t*)&g_ochi[base + j + 2] = h23;
            *(uint32_t*)&g_oclo[base + j]     = l01;
            *(uint32_t*)&g_oclo[base + j + 2] = l23;
        }
    } else {
        const int idx = (bx - 64) * 256 + tid;
        const int t = idx >> 12, kl = idx & 4095;
        float a0 = 0, a1 = 0, a2 = 0, a3 = 0;
#pragma unroll
        for (int j = 0; j < 64; j += 4) {
            a0 += task[t * 64 + j + 0] * tc[(size_t)(j + 0) * 4096 + kl];
            a1 += task[t * 64 + j + 1] * tc[(size_t)(j + 1) * 4096 + kl];
            a2 += task[t * 64 + j + 2] * tc[(size_t)(j + 2) * 4096 + kl];
            a3 += task[t * 64 + j + 3] * tc[(size_t)(j + 3) * 4096 + kl];
        }
        g_W1[idx] = (a0 + a1) + (a2 + a3);
    }
}

// ---------------------------------------------------------------------------
// k_bt: Bt[t][k][n] = sum_j in_core[k][j]*W1[t][j][n] -> bf16 hi/lo [t][n][k].
// ---------------------------------------------------------------------------
__global__ __launch_bounds__(256) void k_bt(const float* __restrict__ in_core) {
    __shared__ float W1s[4096];
    const int bx = blockIdx.x, tid = threadIdx.x;
    const int t = bx >> 4;
    const int row = (bx & 15) * 256 + tid;
    {
        const float4* src = (const float4*)(g_W1 + t * 4096);
        float4* dst = (float4*)W1s;
#pragma unroll
        for (int i = 0; i < 4; i++) dst[tid + i * 256] = src[tid + i * 256];
    }
    __syncthreads();

    u64 acc[32];
#pragma unroll
    for (int i = 0; i < 32; i++) acc[i] = 0ull;

    const float* icr = in_core + (size_t)row * 64;
#pragma unroll
    for (int jc = 0; jc < 4; jc++) {
        float4 a4[4];
#pragma unroll
        for (int q = 0; q < 4; q++) a4[q] = *(const float4*)(icr + jc * 16 + q * 4);
#pragma unroll
        for (int jj = 0; jj < 16; jj++) {
            const int j = jc * 16 + jj;
            float a = ((const float*)a4)[jj];
            u64 a2 = pk2(a, a);
#pragma unroll
            for (int i2 = 0; i2 < 16; i2++) {
                ulonglong2 w = *(const ulonglong2*)&W1s[j * 64 + i2 * 4];
                acc[2 * i2]     = ffma2(a2, w.x, acc[2 * i2]);
                acc[2 * i2 + 1] = ffma2(a2, w.y, acc[2 * i2 + 1]);
            }
        }
    }
#pragma unroll
    for (int i = 0; i < 32; i++) {
        float v0, v1;
        upk2(acc[i], v0, v1);
        __nv_bfloat16 h0 = __float2bfloat16(v0);
        __nv_bfloat16 l0 = __float2bfloat16(v0 - __bfloat162float(h0));
        __nv_bfloat16 h1 = __float2bfloat16(v1);
        __nv_bfloat16 l1 = __float2bfloat16(v1 - __bfloat162float(h1));
        const size_t b0 = ((size_t)t * 64 + 2 * i) * IN_ + row;
        const size_t b1 = ((size_t)t * 64 + 2 * i + 1) * IN_ + row;
        g_Bthi[b0] = h0; g_Btlo[b0] = l0;
        g_Bthi[b1] = h1; g_Btlo[b1] = l1;
    }
}

// ---------------------------------------------------------------------------
// k_fused: per CTA (128 total): rows = t + 8*(g*64 + r), r=0..63 (task t).
// Phase 1: v[64x64] = x @ Bt[t]  (K=4096, 32... 64 chunks, 2-stage cp.async B,
//          A (x) built in registers with inline hi/lo split).  v -> smem.
// Phase 2: y[64x4096] = v @ oc^T streamed in 16 chunks of 256 cols.
// ---------------------------------------------------------------------------
__global__ __launch_bounds__(256, 1) void k_fused(const float* __restrict__ x,
                                                  float* __restrict__ y) {
    extern __shared__ char sm[];
    const uint32_t sb = smem_u32(sm);
    const int tid = threadIdx.x, warp = tid >> 5, lane = tid & 31;
    const int gr = lane >> 2, p = lane & 3;
    const int bx = blockIdx.x, t = bx & 7, g = bx >> 3;
    const int lr = (lane & 7) + ((lane >> 3) & 1) * 8;
    const int lk = (lane >> 4) * 16;

    // ================= phase 1 =================
    const int wm = warp >> 2, wn = warp & 3;      // warp grid 2(m) x 4(n)
    const int m0w = wm * 32, n0w = wn * 16;

    // x row pointers (4 rows per thread: (mt,half))
    const float* xr[4];
#pragma unroll
    for (int rs = 0; rs < 4; rs++) {
        const int r = m0w + (rs >> 1) * 16 + gr + (rs & 1) * 8;
        xr[rs] = x + (size_t)(t + 8 * (g * 64 + r)) * IN_ + 2 * p;
    }

    // B (Bt) cp.async mapping
    const int brow = tid >> 2, bj = tid & 3;
    const __nv_bfloat16* bth = g_Bthi + ((size_t)t * 64 + brow) * IN_;
    const __nv_bfloat16* btl = g_Btlo + ((size_t)t * 64 + brow) * IN_;
    const uint32_t dB1 = sb + brow * RSTR;
    const uint32_t offB1 = (uint32_t)((n0w + lr) * RSTR + lk);

    float2 xv[4][4][2];      // [rowsel][ks][pair]
    float acc[2][2][4];
#pragma unroll
    for (int mt = 0; mt < 2; mt++)
#pragma unroll
        for (int nt = 0; nt < 2; nt++)
            acc[mt][nt][0] = acc[mt][nt][1] = acc[mt][nt][2] = acc[mt][nt][3] = 0.f;

#define P1_BLOAD(st_, c_) do {                                                \
    const uint32_t d = dB1 + (st_) * P1_STG;                                  \
    cpa16(d + bj * 16,        bth + (c_) * 64 + bj * 8);                      \
    cpa16(d + (bj + 4) * 16,  bth + (c_) * 64 + (bj + 4) * 8);                \
    cpa16(d + 9216 + bj * 16,       btl + (c_) * 64 + bj * 8);                \
    cpa16(d + 9216 + (bj + 4) * 16, btl + (c_) * 64 + (bj + 4) * 8);          \
} while (0)

    // prologue: B chunk 0 + x chunk 0
    P1_BLOAD(0, 0);
    CP_COMMIT();
#pragma unroll
    for (int rs = 0; rs < 4; rs++)
#pragma unroll
        for (int ks = 0; ks < 4; ks++) {
            xv[rs][ks][0] = *(const float2*)(xr[rs] + ks * 16);
            xv[rs][ks][1] = *(const float2*)(xr[rs] + ks * 16 + 8);
        }

    for (int c = 0; c < 64; c++) {
        const int s = c & 1;
        CP_WAIT0();
        __syncthreads();
        if (c < 63) { P1_BLOAD(s ^ 1, c + 1); CP_COMMIT(); }
        const uint32_t st = sb + s * P1_STG;
#pragma unroll
        for (int ks = 0; ks < 4; ks++) {
            uint32_t Bh[4], Bl[4];
            ldsm4(Bh, st + offB1 + ks * 32);
            ldsm4(Bl, st + 9216 + offB1 + ks * 32);
#pragma unroll
            for (int mt = 0; mt < 2; mt++) {
                uint32_t Ah[4], Al[4];
                split2(xv[mt * 2 + 0][ks][0].x, xv[mt * 2 + 0][ks][0].y, Ah[0], Al[0]);
                split2(xv[mt * 2 + 1][ks][0].x, xv[mt * 2 + 1][ks][0].y, Ah[1], Al[1]);
                split2(xv[mt * 2 + 0][ks][1].x, xv[mt * 2 + 0][ks][1].y, Ah[2], Al[2]);
                split2(xv[mt * 2 + 1][ks][1].x, xv[mt * 2 + 1][ks][1].y, Ah[3], Al[3]);
                mma16816(acc[mt][0], Ah[0], Ah[1], Ah[2], Ah[3], Bh[0], Bh[2]);
                mma16816(acc[mt][1], Ah[0], Ah[1], Ah[2], Ah[3], Bh[1], Bh[3]);
                mma16816(acc[mt][0], Ah[0], Ah[1], Ah[2], Ah[3], Bl[0], Bl[2]);
                mma16816(acc[mt][1], Ah[0], Ah[1], Ah[2], Ah[3], Bl[1], Bl[3]);
                mma16816(acc[mt][0], Al[0], Al[1], Al[2], Al[3], Bh[0], Bh[2]);
                mma16816(acc[mt][1], Al[0], Al[1], Al[2], Al[3], Bh[1], Bh[3]);
            }
            // prefetch x(chunk c+1) for this ks — xv[..][ks] now dead
            if (c < 63) {
#pragma unroll
                for (int rs = 0; rs < 4; rs++) {
                    const float* sp = xr[rs] + (c + 1) * 64 + ks * 16;
                    xv[rs][ks][0] = *(const float2*)(sp);
                    xv[rs][ks][1] = *(const float2*)(sp + 8);
                }
            }
        }
    }

    // v epilogue: split acc -> vhi/vlo smem
#pragma unroll
    for (int mt = 0; mt < 2; mt++)
#pragma unroll
        for (int nt = 0; nt < 2; nt++) {
            const int col = n0w + nt * 8 + 2 * p;
            const int r0 = m0w + mt * 16 + gr, r1 = r0 + 8;
            uint32_t h, l;
            split2(acc[mt][nt][0], acc[mt][nt][1], h, l);
            *(uint32_t*)(sm + VHI + r0 * RSTR + col * 2) = h;
            *(uint32_t*)(sm + VLO + r0 * RSTR + col * 2) = l;
            split2(acc[mt][nt][2], acc[mt][nt][3], h, l);
            *(uint32_t*)(sm + VHI + r1 * RSTR + col * 2) = h;
            *(uint32_t*)(sm + VLO + r1 * RSTR + col * 2) = l;
        }
    __syncthreads();   // all phase-1 reads/writes done before stage reuse

    // ================= phase 2 =================
    const int wm2 = warp & 1, wn2 = warp >> 1;   // warp grid 2(m) x 4(n)
    const uint32_t aAvh = sb + VHI + (wm2 * 32 + lr) * RSTR + lk;
    const uint32_t aAvl = sb + VLO + (wm2 * 32 + lr) * RSTR + lk;
    const uint32_t offB2 = (uint32_t)((wn2 * 64 + lr) * RSTR + lk);

    const __nv_bfloat16* oh = g_ochi + (size_t)tid * 64;
    const __nv_bfloat16* ol = g_oclo + (size_t)tid * 64;
    const uint32_t dB2 = sb + tid * RSTR;

#define P2_BLOAD(st_, i_) do {                                                \
    const uint32_t d = dB2 + (st_) * P2_STG;                                  \
    const __nv_bfloat16* sh_ = oh + (size_t)(i_) * 256 * 64;                  \
    const __nv_bfloat16* sl_ = ol + (size_t)(i_) * 256 * 64;                  \
    _Pragma("unroll")                                                         \
    for (int j = 0; j < 8; j++) cpa16(d + j * 16, sh_ + j * 8);               \
    _Pragma("unroll")                                                         \
    for (int j = 0; j < 8; j++) cpa16(d + 36864 + j * 16, sl_ + j * 8);       \
} while (0)

    P2_BLOAD(0, 0);
    CP_COMMIT();

    const size_t growbase = (size_t)t + 8 * (size_t)(g * 64);

    for (int i = 0; i < 16; i++) {
        const int s = i & 1;
        CP_WAIT0();
        __syncthreads();
        if (i < 15) { P2_BLOAD(s ^ 1, i + 1); CP_COMMIT(); }
        const uint32_t st = sb + s * P2_STG;

        float a2[2][8][4];
#pragma unroll
        for (int mt = 0; mt < 2; mt++)
#pragma unroll
            for (int nt = 0; nt < 8; nt++)
                a2[mt][nt][0] = a2[mt][nt][1] = a2[mt][nt][2] = a2[mt][nt][3] = 0.f;

#pragma unroll
        for (int ks = 0; ks < 4; ks++) {
            const uint32_t ka = ks * 32;
            uint32_t Avh[2][4], Avl[2][4], B[4][4];
            ldsm4(Avh[0], aAvh + ka);
            ldsm4(Avh[1], aAvh + 16 * RSTR + ka);
            ldsm4(Avl[0], aAvl + ka);
            ldsm4(Avl[1], aAvl + 16 * RSTR + ka);
#pragma unroll
            for (int j = 0; j < 4; j++)
                ldsm4(B[j], st + offB2 + j * 16 * RSTR + ka);
            // hi*hi + lo*hi (B = Bh)
#pragma unroll
            for (int mt = 0; mt < 2; mt++)
#pragma unroll
                for (int j = 0; j < 4; j++) {
                    mma16816(a2[mt][2 * j],     Avh[mt][0], Avh[mt][1], Avh[mt][2], Avh[mt][3], B[j][0], B[j][2]);
                    mma16816(a2[mt][2 * j + 1], Avh[mt][0], Avh[mt][1], Avh[mt][2], Avh[mt][3], B[j][1], B[j][3]);
                    mma16816(a2[mt][2 * j],     Avl[mt][0], Avl[mt][1], Avl[mt][2], Avl[mt][3], B[j][0], B[j][2]);
                    mma16816(a2[mt][2 * j + 1], Avl[mt][0], Avl[mt][1], Avl[mt][2], Avl[mt][3], B[j][1], B[j][3]);
                }
            // hi*lo (reload B = Bl)
#pragma unroll
            for (int j = 0; j < 4; j++)
                ldsm4(B[j], st + 36864 + offB2 + j * 16 * RSTR + ka);
#pragma unroll
            for (int mt = 0; mt < 2; mt++)
#pragma unroll
                for (int j = 0; j < 4; j++) {
                    mma16816(a2[mt][2 * j],     Avh[mt][0], Avh[mt][1], Avh[mt][2], Avh[mt][3], B[j][0], B[j][2]);
                    mma16816(a2[mt][2 * j + 1], Avh[mt][0], Avh[mt][1], Avh[mt][2], Avh[mt][3], B[j][1], B[j][3]);
                }
        }

        // store y chunk
#pragma unroll
        for (int mt = 0; mt < 2; mt++) {
            const int r0 = wm2 * 32 + mt * 16 + gr;
            const size_t grow0 = growbase + 8 * (size_t)r0;
            const size_t grow1 = grow0 + 64;
#pragma unroll
            for (int nt = 0; nt < 8; nt++) {
                const int col = i * 256 + wn2 * 64 + nt * 8 + 2 * p;
                *(float2*)&y[grow0 * OUT_ + col] = make_float2(a2[mt][nt][0], a2[mt][nt][1]);
                *(float2*)&y[grow1 * OUT_ + col] = make_float2(a2[mt][nt][2], a2[mt][nt][3]);
            }
        }
    }
}

// ---------------------------------------------------------------------------
extern "C" void kernel_launch(void* const* d_in, const int* in_sizes, int n_in,
                              void* d_out, int out_size) {
    const float* x        = (const float*)d_in[0];
    const float* tc       = (const float*)d_in[1];
    const float* task     = (const float*)d_in[2];
    const float* in_core  = (const float*)d_in[3];
    const float* out_core = (const float*)d_in[4];
    float* y = (float*)d_out;

    cudaFuncSetAttribute(k_fused, cudaFuncAttributeMaxDynamicSharedMemorySize, FU_SMEM);

    k_pre1<<<192, 256>>>(task, tc, out_core);
    k_bt<<<128, 256>>>(in_core);
    k_fused<<<128, 256, FU_SMEM>>>(x, y);
}

// round 9
// speedup vs baseline: 1.4766x; 1.4766x over previous
#include <cuda_runtime.h>
#include <cuda_bf16.h>
#include <cuda_fp16.h>
#include <cstdint>

#define BT_   8192
#define IN_   4096
#define OUT_  4096
#define R_    64
#define T_    8

// ---------------- device scratch ----------------
__device__ float          g_W1[T_ * R_ * R_];
__device__ __nv_bfloat16  g_Bthi[T_ * R_ * IN_];   // Bt = in_core@W1 : [t][n][k]
__device__ __nv_bfloat16  g_Btlo[T_ * R_ * IN_];
__device__ __half         g_och[OUT_ * R_];        // out_core fp16 [n][k]
__device__ float          g_vpart[2][BT_ * R_];    // split-K partials of v
__device__ __half         g_vhi[BT_ * R_];         // v fp16 hi
__device__ __half         g_vlo[BT_ * R_];         // v fp16 lo

typedef unsigned long long u64;

// ---------- packed f32x2 ----------
__device__ __forceinline__ u64 pk2(float lo, float hi) {
    u64 r; asm("mov.b64 %0, {%1, %2};" : "=l"(r) : "f"(lo), "f"(hi)); return r;
}
__device__ __forceinline__ void upk2(u64 v, float& lo, float& hi) {
    asm("mov.b64 {%0, %1}, %2;" : "=f"(lo), "=f"(hi) : "l"(v));
}
__device__ __forceinline__ u64 ffma2(u64 a, u64 b, u64 c) {
    u64 d; asm("fma.rn.f32x2 %0, %1, %2, %3;" : "=l"(d) : "l"(a), "l"(b), "l"(c)); return d;
}

// ---------- fp32 -> bf16 hi/lo split ----------
__device__ __forceinline__ void split4(float4 v, uint32_t& h01, uint32_t& h23,
                                       uint32_t& l01, uint32_t& l23) {
    __nv_bfloat162 h0 = __floats2bfloat162_rn(v.x, v.y);
    __nv_bfloat162 h1 = __floats2bfloat162_rn(v.z, v.w);
    float rx = v.x - __bfloat162float(h0.x);
    float ry = v.y - __bfloat162float(h0.y);
    float rz = v.z - __bfloat162float(h1.x);
    float rw = v.w - __bfloat162float(h1.y);
    __nv_bfloat162 l0 = __floats2bfloat162_rn(rx, ry);
    __nv_bfloat162 l1 = __floats2bfloat162_rn(rz, rw);
    h01 = *(uint32_t*)&h0; h23 = *(uint32_t*)&h1;
    l01 = *(uint32_t*)&l0; l23 = *(uint32_t*)&l1;
}

// ---------- fp32 -> fp16 hi/lo split ----------
__device__ __forceinline__ void split2h(float a, float b, uint32_t& h, uint32_t& l) {
    __half2 hh = __floats2half2_rn(a, b);
    float ra = a - __half2float(__low2half(hh));
    float rb = b - __half2float(__high2half(hh));
    __half2 ll = __floats2half2_rn(ra, rb);
    h = *(uint32_t*)&hh; l = *(uint32_t*)&ll;
}

// ---------- tensor-core primitives (base-ISA, sm_103-safe) ----------
__device__ __forceinline__ void mma16816(float* c, uint32_t a0, uint32_t a1,
                                         uint32_t a2, uint32_t a3,
                                         uint32_t b0, uint32_t b1) {
    asm volatile(
        "mma.sync.aligned.m16n8k16.row.col.f32.bf16.bf16.f32 "
        "{%0,%1,%2,%3}, {%4,%5,%6,%7}, {%8,%9}, {%0,%1,%2,%3};"
        : "+f"(c[0]), "+f"(c[1]), "+f"(c[2]), "+f"(c[3])
        : "r"(a0), "r"(a1), "r"(a2), "r"(a3), "r"(b0), "r"(b1));
}
__device__ __forceinline__ void mma16816h(float* c, uint32_t a0, uint32_t a1,
                                          uint32_t a2, uint32_t a3,
                                          uint32_t b0, uint32_t b1) {
    asm volatile(
        "mma.sync.aligned.m16n8k16.row.col.f32.f16.f16.f32 "
        "{%0,%1,%2,%3}, {%4,%5,%6,%7}, {%8,%9}, {%0,%1,%2,%3};"
        : "+f"(c[0]), "+f"(c[1]), "+f"(c[2]), "+f"(c[3])
        : "r"(a0), "r"(a1), "r"(a2), "r"(a3), "r"(b0), "r"(b1));
}
__device__ __forceinline__ void ldsm4(uint32_t* r, uint32_t saddr) {
    asm volatile("ldmatrix.sync.aligned.m8n8.x4.shared.b16 {%0,%1,%2,%3}, [%4];"
                 : "=r"(r[0]), "=r"(r[1]), "=r"(r[2]), "=r"(r[3]) : "r"(saddr));
}
__device__ __forceinline__ void cpa16(uint32_t dst, const void* src) {
    asm volatile("cp.async.cg.shared.global [%0], [%1], 16;" :: "r"(dst), "l"(src));
}
#define CP_COMMIT() asm volatile("cp.async.commit_group;" ::: "memory")
#define CP_WAIT0()  asm volatile("cp.async.wait_group 0;" ::: "memory")

__device__ __forceinline__ uint32_t smem_u32(const void* p) {
    uint32_t a;
    asm("{ .reg .u64 t; cvta.to.shared.u64 t, %1; cvt.u32.u64 %0, t; }" : "=r"(a) : "l"(p));
    return a;
}

// row stride in all smem tile matrices: 144 bytes (36 words) -> LDSM conflict-free
#define RSTR 144

// ---------------------------------------------------------------------------
// k_pre1: out_core fp16 (bx<64) + W1 (bx in [64,192)).
// ---------------------------------------------------------------------------
__global__ __launch_bounds__(256) void k_pre1(const float* __restrict__ task,
                                              const float* __restrict__ tc,
                                              const float* __restrict__ out_core) {
    const int bx = blockIdx.x, tid = threadIdx.x;
    if (bx < 64) {
        const size_t base = (size_t)bx * 4096 + (size_t)tid * 16;
#pragma unroll
        for (int j = 0; j < 16; j += 4) {
            float4 v = *(const float4*)&out_core[base + j];
            __half2 h0 = __floats2half2_rn(v.x, v.y);
            __half2 h1 = __floats2half2_rn(v.z, v.w);
            *(uint32_t*)&g_och[base + j]     = *(uint32_t*)&h0;
            *(uint32_t*)&g_och[base + j + 2] = *(uint32_t*)&h1;
        }
    } else {
        const int idx = (bx - 64) * 256 + tid;
        const int t = idx >> 12, kl = idx & 4095;
        float a0 = 0, a1 = 0, a2 = 0, a3 = 0;
#pragma unroll
        for (int j = 0; j < 64; j += 4) {
            a0 += task[t * 64 + j + 0] * tc[(size_t)(j + 0) * 4096 + kl];
            a1 += task[t * 64 + j + 1] * tc[(size_t)(j + 1) * 4096 + kl];
            a2 += task[t * 64 + j + 2] * tc[(size_t)(j + 2) * 4096 + kl];
            a3 += task[t * 64 + j + 3] * tc[(size_t)(j + 3) * 4096 + kl];
        }
        g_W1[idx] = (a0 + a1) + (a2 + a3);
    }
}

// ---------------------------------------------------------------------------
// k_bt: Bt[t][k][n] = sum_j in_core[k][j]*W1[t][j][n] -> bf16 hi/lo [t][n][k].
// ---------------------------------------------------------------------------
__global__ __launch_bounds__(256) void k_bt(const float* __restrict__ in_core) {
    __shared__ float W1s[4096];
    const int bx = blockIdx.x, tid = threadIdx.x;
    const int t = bx >> 4;
    const int row = (bx & 15) * 256 + tid;      // k index
    {
        const float4* src = (const float4*)(g_W1 + t * 4096);
        float4* dst = (float4*)W1s;
#pragma unroll
        for (int i = 0; i < 4; i++) dst[tid + i * 256] = src[tid + i * 256];
    }
    __syncthreads();

    u64 acc[32];
#pragma unroll
    for (int i = 0; i < 32; i++) acc[i] = 0ull;

    const float* icr = in_core + (size_t)row * 64;
#pragma unroll
    for (int jc = 0; jc < 4; jc++) {
        float4 a4[4];
#pragma unroll
        for (int q = 0; q < 4; q++) a4[q] = *(const float4*)(icr + jc * 16 + q * 4);
#pragma unroll
        for (int jj = 0; jj < 16; jj++) {
            const int j = jc * 16 + jj;
            float a = ((const float*)a4)[jj];
            u64 a2 = pk2(a, a);
#pragma unroll
            for (int i2 = 0; i2 < 16; i2++) {
                ulonglong2 w = *(const ulonglong2*)&W1s[j * 64 + i2 * 4];
                acc[2 * i2]     = ffma2(a2, w.x, acc[2 * i2]);
                acc[2 * i2 + 1] = ffma2(a2, w.y, acc[2 * i2 + 1]);
            }
        }
    }
#pragma unroll
    for (int i = 0; i < 32; i++) {
        float v0, v1;
        upk2(acc[i], v0, v1);
        __nv_bfloat16 h0 = __float2bfloat16(v0);
        __nv_bfloat16 l0 = __float2bfloat16(v0 - __bfloat162float(h0));
        __nv_bfloat16 h1 = __float2bfloat16(v1);
        __nv_bfloat16 l1 = __float2bfloat16(v1 - __bfloat162float(h1));
        const size_t b0 = ((size_t)t * 64 + 2 * i) * IN_ + row;
        const size_t b1 = ((size_t)t * 64 + 2 * i + 1) * IN_ + row;
        g_Bthi[b0] = h0; g_Btlo[b0] = l0;
        g_Bthi[b1] = h1; g_Btlo[b1] = l1;
    }
}

// ---------------------------------------------------------------------------
// k_gemm1: v_partial = x @ Bt[t]  (tile 64m x 64n, K-slice 2048 = 32 chunks
// of 64). 256 CTAs: mtile = bx>>1 (t = mtile&7, g = mtile>>3), kslice = bx&1.
// Pipelined: LDG x(c+1) -> regs BEFORE compute(c); split+STS AFTER compute(c).
// smem/stage 36864B: AH@0 AL@9216 BH@18432 BL@27648;  2 stages = 73728B.
// ---------------------------------------------------------------------------
#define G1_SMEM 73728

__global__ __launch_bounds__(256, 2) void k_gemm1(const float* __restrict__ x) {
    extern __shared__ char sm[];
    const uint32_t sb = smem_u32(sm);
    const int tid = threadIdx.x, warp = tid >> 5, lane = tid & 31;
    const int gr = lane >> 2, p = lane & 3;
    const int bx = blockIdx.x;
    const int mtile = bx >> 1, ksl = bx & 1;
    const int t = mtile & 7, g = mtile >> 3;
    const int koff = ksl * 2048;

    // x loader mapping: 4 threads per row
    const int lrow = tid >> 2, lq = tid & 3;
    const float* xrp = x + (size_t)(t + 8 * (g * 64 + lrow)) * IN_ + koff;

    // B cp.async mapping
    const int bn = tid >> 2, bj = tid & 3;
    const __nv_bfloat16* bth = g_Bthi + ((size_t)t * 64 + bn) * IN_ + koff;
    const __nv_bfloat16* btl = g_Btlo + ((size_t)t * 64 + bn) * IN_ + koff;
    const uint32_t dB = sb + 18432 + bn * RSTR;

    // ldmatrix lane roles
    const int m0 = (warp >> 1) * 16, n0 = (warp & 1) * 32;
    const int lr = (lane & 7) + ((lane >> 3) & 1) * 8;
    const int lk = (lane >> 4) * 16;
    const uint32_t offA = (uint32_t)((m0 + lr) * RSTR + lk);
    const uint32_t offB = (uint32_t)((n0 + lr) * RSTR + lk);

    float acc[4][4];
#pragma unroll
    for (int i = 0; i < 4; i++) acc[i][0] = acc[i][1] = acc[i][2] = acc[i][3] = 0.f;

    float4 xv[4];

#define G1_BLOAD(st_, c_) do {                                                \
    const uint32_t d = dB + (st_) * 36864;                                    \
    cpa16(d + bj * 16,        bth + (c_) * 64 + bj * 8);                      \
    cpa16(d + (bj + 4) * 16,  bth + (c_) * 64 + (bj + 4) * 8);                \
    cpa16(d + 9216 + bj * 16,       btl + (c_) * 64 + bj * 8);                \
    cpa16(d + 9216 + (bj + 4) * 16, btl + (c_) * 64 + (bj + 4) * 8);          \
} while (0)

#define G1_XLDG(c_) do {                                                      \
    const float* srcx = xrp + (c_) * 64;                                      \
    _Pragma("unroll")                                                         \
    for (int seg = 0; seg < 4; seg++)                                         \
        xv[seg] = *(const float4*)(srcx + seg * 16 + lq * 4);                 \
} while (0)

#define G1_XSTS(st_) do {                                                     \
    char* ah = sm + (st_) * 36864 + lrow * RSTR + lq * 8;                     \
    _Pragma("unroll")                                                         \
    for (int seg = 0; seg < 4; seg++) {                                       \
        uint32_t h01, h23, l01, l23;                                          \
        split4(xv[seg], h01, h23, l01, l23);                                  \
        *(uint2*)(ah + seg * 32)        = make_uint2(h01, h23);               \
        *(uint2*)(ah + 9216 + seg * 32) = make_uint2(l01, l23);               \
    }                                                                         \
} while (0)

    // prologue: chunk 0 -> stage 0
    G1_BLOAD(0, 0);
    CP_COMMIT();
    G1_XLDG(0);
    G1_XSTS(0);

    for (int c = 0; c < 32; c++) {
        const int s = c & 1;
        CP_WAIT0();
        __syncthreads();
        if (c < 31) {
            G1_BLOAD(s ^ 1, c + 1);
            CP_COMMIT();
            G1_XLDG(c + 1);          // LDG in flight during compute below
        }
        // compute chunk c from stage s
        const uint32_t st = sb + s * 36864;
#pragma unroll
        for (int ks = 0; ks < 4; ks++) {
            const uint32_t ka = ks * 32;
            uint32_t Ah[4], Al[4], B0[4], B1[4], L0[4], L1[4];
            ldsm4(Ah, st + offA + ka);
            ldsm4(B0, st + 18432 + offB + ka);
            ldsm4(B1, st + 18432 + 16 * RSTR + offB + ka);
            ldsm4(Al, st + 9216 + offA + ka);
            ldsm4(L0, st + 27648 + offB + ka);
            ldsm4(L1, st + 27648 + 16 * RSTR + offB + ka);
            // hi*hi
            mma16816(acc[0], Ah[0], Ah[1], Ah[2], Ah[3], B0[0], B0[2]);
            mma16816(acc[1], Ah[0], Ah[1], Ah[2], Ah[3], B0[1], B0[3]);
            mma16816(acc[2], Ah[0], Ah[1], Ah[2], Ah[3], B1[0], B1[2]);
            mma16816(acc[3], Ah[0], Ah[1], Ah[2], Ah[3], B1[1], B1[3]);
            // lo*hi
            mma16816(acc[0], Al[0], Al[1], Al[2], Al[3], B0[0], B0[2]);
            mma16816(acc[1], Al[0], Al[1], Al[2], Al[3], B0[1], B0[3]);
            mma16816(acc[2], Al[0], Al[1], Al[2], Al[3], B1[0], B1[2]);
            mma16816(acc[3], Al[0], Al[1], Al[2], Al[3], B1[1], B1[3]);
            // hi*lo
            mma16816(acc[0], Ah[0], Ah[1], Ah[2], Ah[3], L0[0], L0[2]);
            mma16816(acc[1], Ah[0], Ah[1], Ah[2], Ah[3], L0[1], L0[3]);
            mma16816(acc[2], Ah[0], Ah[1], Ah[2], Ah[3], L1[0], L1[2]);
            mma16816(acc[3], Ah[0], Ah[1], Ah[2], Ah[3], L1[1], L1[3]);
        }
        if (c < 31) G1_XSTS(s ^ 1);   // split + store AFTER compute (LDG hidden)
    }

    // store partials (deterministic plain stores)
    float* vp = g_vpart[ksl];
    const size_t r0 = (size_t)(t + 8 * (g * 64 + m0 + gr));
    const size_t r1 = r0 + 64;   // row + 8 in tile = +64 global
#pragma unroll
    for (int nt = 0; nt < 4; nt++) {
        const int col = n0 + nt * 8 + 2 * p;
        *(float2*)&vp[r0 * 64 + col] = make_float2(acc[nt][0], acc[nt][1]);
        *(float2*)&vp[r1 * 64 + col] = make_float2(acc[nt][2], acc[nt][3]);
    }
}

// ---------------------------------------------------------------------------
// k_vred: v = sum of 2 partials, split to fp16 hi/lo.  512 blocks x 256 thr.
// ---------------------------------------------------------------------------
__global__ __launch_bounds__(256) void k_vred() {
    const int idx = blockIdx.x * 256 + threadIdx.x;   // float4 index
    const float4* p0 = (const float4*)g_vpart[0];
    const float4* p1 = (const float4*)g_vpart[1];
    float4 a = p0[idx], b = p1[idx];
    float4 s = make_float4(a.x + b.x, a.y + b.y, a.z + b.z, a.w + b.w);
    uint32_t h01, l01, h23, l23;
    split2h(s.x, s.y, h01, l01);
    split2h(s.z, s.w, h23, l23);
    *(uint2*)&g_vhi[(size_t)idx * 4] = make_uint2(h01, h23);
    *(uint2*)&g_vlo[(size_t)idx * 4] = make_uint2(l01, l23);
}

// ---------------------------------------------------------------------------
// k_gemm2: y = v @ och^T (fp16 2-term: vh*oc + vl*oc).  Tile 128x128, K=64,
// warp tile 64x32.  smem: AH@0 AL@18432 BH@36864 = 55296B.  grid (32, 64).
// ---------------------------------------------------------------------------
#define G2_SMEM 55296

__global__ __launch_bounds__(256, 2) void k_gemm2(float* __restrict__ y) {
    extern __shared__ char sm[];
    const uint32_t sb = smem_u32(sm);
    const int tid = threadIdx.x, warp = tid >> 5, lane = tid & 31;
    const int gr = lane >> 2, p = lane & 3;
    const int n0b = blockIdx.x * 128, m0b = blockIdx.y * 128;

    {   // cp.async all 3 tiles
        const int row = tid >> 1, q = (tid & 1) * 4;
        const uint32_t drow = sb + row * RSTR;
        const __half* sa  = g_vhi + (size_t)(m0b + row) * 64;
        const __half* sal = g_vlo + (size_t)(m0b + row) * 64;
        const __half* sbh = g_och + (size_t)(n0b + row) * 64;
#pragma unroll
        for (int j = 0; j < 4; j++) {
            cpa16(drow + (q + j) * 16,         sa  + (q + j) * 8);
            cpa16(drow + 18432 + (q + j) * 16, sal + (q + j) * 8);
            cpa16(drow + 36864 + (q + j) * 16, sbh + (q + j) * 8);
        }
    }
    CP_COMMIT();
    CP_WAIT0();
    __syncthreads();

    const int m0 = (warp >> 2) * 64, n0 = (warp & 3) * 32;
    const int lr = (lane & 7) + ((lane >> 3) & 1) * 8;
    const int lk = (lane >> 4) * 16;
    const uint32_t offA = (uint32_t)((m0 + lr) * RSTR + lk);
    const uint32_t offB = (uint32_t)((n0 + lr) * RSTR + lk);

    float acc[4][4][4];
#pragma unroll
    for (int mt = 0; mt < 4; mt++)
#pragma unroll
        for (int nt = 0; nt < 4; nt++)
            acc[mt][nt][0] = acc[mt][nt][1] = acc[mt][nt][2] = acc[mt][nt][3] = 0.f;

#pragma unroll
    for (int ks = 0; ks < 4; ks++) {
        const uint32_t ka = ks * 32;
        uint32_t Ah[4][4], Al[4][4], B0[4], B1[4];
#pragma unroll
        for (int mt = 0; mt < 4; mt++)
            ldsm4(Ah[mt], sb + offA + mt * 16 * RSTR + ka);
        ldsm4(B0, sb + 36864 + offB + ka);
        ldsm4(B1, sb + 36864 + 16 * RSTR + offB + ka);
        // vh * oc
#pragma unroll
        for (int mt = 0; mt < 4; mt++) {
            mma16816h(acc[mt][0], Ah[mt][0], Ah[mt][1], Ah[mt][2], Ah[mt][3], B0[0], B0[2]);
            mma16816h(acc[mt][1], Ah[mt][0], Ah[mt][1], Ah[mt][2], Ah[mt][3], B0[1], B0[3]);
            mma16816h(acc[mt][2], Ah[mt][0], Ah[mt][1], Ah[mt][2], Ah[mt][3], B1[0], B1[2]);
            mma16816h(acc[mt][3], Ah[mt][0], Ah[mt][1], Ah[mt][2], Ah[mt][3], B1[1], B1[3]);
        }
        // vl * oc
#pragma unroll
        for (int mt = 0; mt < 4; mt++)
            ldsm4(Al[mt], sb + 18432 + offA + mt * 16 * RSTR + ka);
#pragma unroll
        for (int mt = 0; mt < 4; mt++) {
            mma16816h(acc[mt][0], Al[mt][0], Al[mt][1], Al[mt][2], Al[mt][3], B0[0], B0[2]);
            mma16816h(acc[mt][1], Al[mt][0], Al[mt][1], Al[mt][2], Al[mt][3], B0[1], B0[3]);
            mma16816h(acc[mt][2], Al[mt][0], Al[mt][1], Al[mt][2], Al[mt][3], B1[0], B1[2]);
            mma16816h(acc[mt][3], Al[mt][0], Al[mt][1], Al[mt][2], Al[mt][3], B1[1], B1[3]);
        }
    }

#pragma unroll
    for (int mt = 0; mt < 4; mt++) {
#pragma unroll
        for (int nt = 0; nt < 4; nt++) {
            const int row = m0b + m0 + mt * 16 + gr;
            const int col = n0b + n0 + nt * 8 + 2 * p;
            *(float2*)&y[(size_t)row * OUT_ + col] =
                make_float2(acc[mt][nt][0], acc[mt][nt][1]);
            *(float2*)&y[(size_t)(row + 8) * OUT_ + col] =
                make_float2(acc[mt][nt][2], acc[mt][nt][3]);
        }
    }
}

// ---------------------------------------------------------------------------
extern "C" void kernel_launch(void* const* d_in, const int* in_sizes, int n_in,
                              void* d_out, int out_size) {
    const float* x        = (const float*)d_in[0];
    const float* tc       = (const float*)d_in[1];
    const float* task     = (const float*)d_in[2];
    const float* in_core  = (const float*)d_in[3];
    const float* out_core = (const float*)d_in[4];
    float* y = (float*)d_out;

    cudaFuncSetAttribute(k_gemm1, cudaFuncAttributeMaxDynamicSharedMemorySize, G1_SMEM);
    cudaFuncSetAttribute(k_gemm2, cudaFuncAttributeMaxDynamicSharedMemorySize, G2_SMEM);

    k_pre1<<<192, 256>>>(task, tc, out_core);
    k_bt<<<128, 256>>>(in_core);
    k_gemm1<<<256, 256, G1_SMEM>>>(x);
    k_vred<<<512, 256>>>();
    k_gemm2<<<dim3(OUT_ / 128, BT_ / 128), 256, G2_SMEM>>>(y);
}

// round 10
// speedup vs baseline: 1.7049x; 1.1545x over previous
#include <cuda_runtime.h>
#include <cuda_bf16.h>
#include <cuda_fp16.h>
#include <cstdint>

#define BT_   8192
#define IN_   4096
#define OUT_  4096
#define R_    64
#define T_    8

// ---------------- device scratch ----------------
__device__ float          g_W1[T_ * R_ * R_];
__device__ __half         g_Bth[T_ * R_ * IN_];    // Bt = in_core@W1 : fp16 [t][n][k]
__device__ __half         g_och[OUT_ * R_];        // out_core fp16 [n][k]
__device__ float          g_vpart[2][BT_ * R_];    // split-K partials of v
__device__ __half         g_vhi[BT_ * R_];         // v fp16 hi
__device__ __half         g_vlo[BT_ * R_];         // v fp16 lo

typedef unsigned long long u64;

// ---------- packed f32x2 ----------
__device__ __forceinline__ u64 pk2(float lo, float hi) {
    u64 r; asm("mov.b64 %0, {%1, %2};" : "=l"(r) : "f"(lo), "f"(hi)); return r;
}
__device__ __forceinline__ void upk2(u64 v, float& lo, float& hi) {
    asm("mov.b64 {%0, %1}, %2;" : "=f"(lo), "=f"(hi) : "l"(v));
}
__device__ __forceinline__ u64 ffma2(u64 a, u64 b, u64 c) {
    u64 d; asm("fma.rn.f32x2 %0, %1, %2, %3;" : "=l"(d) : "l"(a), "l"(b), "l"(c)); return d;
}

// ---------- fp32 -> fp16 hi/lo split ----------
__device__ __forceinline__ void split2h(float a, float b, uint32_t& h, uint32_t& l) {
    __half2 hh = __floats2half2_rn(a, b);
    float ra = a - __half2float(__low2half(hh));
    float rb = b - __half2float(__high2half(hh));
    __half2 ll = __floats2half2_rn(ra, rb);
    h = *(uint32_t*)&hh; l = *(uint32_t*)&ll;
}

// ---------- tensor-core primitives (base-ISA, sm_103-safe) ----------
__device__ __forceinline__ void mma16816h(float* c, uint32_t a0, uint32_t a1,
                                          uint32_t a2, uint32_t a3,
                                          uint32_t b0, uint32_t b1) {
    asm volatile(
        "mma.sync.aligned.m16n8k16.row.col.f32.f16.f16.f32 "
        "{%0,%1,%2,%3}, {%4,%5,%6,%7}, {%8,%9}, {%0,%1,%2,%3};"
        : "+f"(c[0]), "+f"(c[1]), "+f"(c[2]), "+f"(c[3])
        : "r"(a0), "r"(a1), "r"(a2), "r"(a3), "r"(b0), "r"(b1));
}
__device__ __forceinline__ void ldsm4(uint32_t* r, uint32_t saddr) {
    asm volatile("ldmatrix.sync.aligned.m8n8.x4.shared.b16 {%0,%1,%2,%3}, [%4];"
                 : "=r"(r[0]), "=r"(r[1]), "=r"(r[2]), "=r"(r[3]) : "r"(saddr));
}
__device__ __forceinline__ void cpa16(uint32_t dst, const void* src) {
    asm volatile("cp.async.cg.shared.global [%0], [%1], 16;" :: "r"(dst), "l"(src));
}
#define CP_COMMIT() asm volatile("cp.async.commit_group;" ::: "memory")
#define CP_WAIT0()  asm volatile("cp.async.wait_group 0;" ::: "memory")

__device__ __forceinline__ uint32_t smem_u32(const void* p) {
    uint32_t a;
    asm("{ .reg .u64 t; cvta.to.shared.u64 t, %1; cvt.u32.u64 %0, t; }" : "=r"(a) : "l"(p));
    return a;
}

// row stride in all smem tile matrices: 144 bytes (36 words) -> LDSM conflict-free
#define RSTR 144

// ---------------------------------------------------------------------------
// k_pre1: out_core fp16 (bx<64) + W1 (bx in [64,192)).
// ---------------------------------------------------------------------------
__global__ __launch_bounds__(256) void k_pre1(const float* __restrict__ task,
                                              const float* __restrict__ tc,
                                              const float* __restrict__ out_core) {
    const int bx = blockIdx.x, tid = threadIdx.x;
    if (bx < 64) {
        const size_t base = (size_t)bx * 4096 + (size_t)tid * 16;
#pragma unroll
        for (int j = 0; j < 16; j += 4) {
            float4 v = *(const float4*)&out_core[base + j];
            __half2 h0 = __floats2half2_rn(v.x, v.y);
            __half2 h1 = __floats2half2_rn(v.z, v.w);
            *(uint32_t*)&g_och[base + j]     = *(uint32_t*)&h0;
            *(uint32_t*)&g_och[base + j + 2] = *(uint32_t*)&h1;
        }
    } else {
        const int idx = (bx - 64) * 256 + tid;
        const int t = idx >> 12, kl = idx & 4095;
        float a0 = 0, a1 = 0, a2 = 0, a3 = 0;
#pragma unroll
        for (int j = 0; j < 64; j += 4) {
            a0 += task[t * 64 + j + 0] * tc[(size_t)(j + 0) * 4096 + kl];
            a1 += task[t * 64 + j + 1] * tc[(size_t)(j + 1) * 4096 + kl];
            a2 += task[t * 64 + j + 2] * tc[(size_t)(j + 2) * 4096 + kl];
            a3 += task[t * 64 + j + 3] * tc[(size_t)(j + 3) * 4096 + kl];
        }
        g_W1[idx] = (a0 + a1) + (a2 + a3);
    }
}

// ---------------------------------------------------------------------------
// k_bt: Bt[t][k][n] = sum_j in_core[k][j]*W1[t][j][n] -> fp16 [t][n][k].
// ---------------------------------------------------------------------------
__global__ __launch_bounds__(256) void k_bt(const float* __restrict__ in_core) {
    __shared__ float W1s[4096];
    const int bx = blockIdx.x, tid = threadIdx.x;
    const int t = bx >> 4;
    const int row = (bx & 15) * 256 + tid;      // k index
    {
        const float4* src = (const float4*)(g_W1 + t * 4096);
        float4* dst = (float4*)W1s;
#pragma unroll
        for (int i = 0; i < 4; i++) dst[tid + i * 256] = src[tid + i * 256];
    }
    __syncthreads();

    u64 acc[32];
#pragma unroll
    for (int i = 0; i < 32; i++) acc[i] = 0ull;

    const float* icr = in_core + (size_t)row * 64;
#pragma unroll
    for (int jc = 0; jc < 4; jc++) {
        float4 a4[4];
#pragma unroll
        for (int q = 0; q < 4; q++) a4[q] = *(const float4*)(icr + jc * 16 + q * 4);
#pragma unroll
        for (int jj = 0; jj < 16; jj++) {
            const int j = jc * 16 + jj;
            float a = ((const float*)a4)[jj];
            u64 a2 = pk2(a, a);
#pragma unroll
            for (int i2 = 0; i2 < 16; i2++) {
                ulonglong2 w = *(const ulonglong2*)&W1s[j * 64 + i2 * 4];
                acc[2 * i2]     = ffma2(a2, w.x, acc[2 * i2]);
                acc[2 * i2 + 1] = ffma2(a2, w.y, acc[2 * i2 + 1]);
            }
        }
    }
    // fp16 round + transposed store: Bt[t][n][row]
#pragma unroll
    for (int i = 0; i < 32; i++) {
        float v0, v1;
        upk2(acc[i], v0, v1);
        const size_t b0 = ((size_t)t * 64 + 2 * i) * IN_ + row;
        const size_t b1 = ((size_t)t * 64 + 2 * i + 1) * IN_ + row;
        g_Bth[b0] = __float2half(v0);
        g_Bth[b1] = __float2half(v1);
    }
}

// ---------------------------------------------------------------------------
// k_gemm1: v_partial = x @ Bt[t]  (tile 64m x 64n, K-slice 2048 = 32 chunks
// of 64). 256 CTAs: mtile = bx>>1 (t = mtile&7, g = mtile>>3), kslice = bx&1.
// fp16 2-term: (xh + xl) @ Bt_fp16.  Pipelined as in R9.
// smem/stage 27648B: AH@0 AL@9216 BH@18432;  2 stages = 55296B.
// ---------------------------------------------------------------------------
#define G1_STG  27648
#define G1_SMEM 55296

__global__ __launch_bounds__(256, 2) void k_gemm1(const float* __restrict__ x) {
    extern __shared__ char sm[];
    const uint32_t sb = smem_u32(sm);
    const int tid = threadIdx.x, warp = tid >> 5, lane = tid & 31;
    const int gr = lane >> 2, p = lane & 3;
    const int bx = blockIdx.x;
    const int mtile = bx >> 1, ksl = bx & 1;
    const int t = mtile & 7, g = mtile >> 3;
    const int koff = ksl * 2048;

    // x loader mapping: 4 threads per row
    const int lrow = tid >> 2, lq = tid & 3;
    const float* xrp = x + (size_t)(t + 8 * (g * 64 + lrow)) * IN_ + koff;

    // B cp.async mapping
    const int bn = tid >> 2, bj = tid & 3;
    const __half* bth = g_Bth + ((size_t)t * 64 + bn) * IN_ + koff;
    const uint32_t dB = sb + 18432 + bn * RSTR;

    // ldmatrix lane roles
    const int m0 = (warp >> 1) * 16, n0 = (warp & 1) * 32;
    const int lr = (lane & 7) + ((lane >> 3) & 1) * 8;
    const int lk = (lane >> 4) * 16;
    const uint32_t offA = (uint32_t)((m0 + lr) * RSTR + lk);
    const uint32_t offB = (uint32_t)((n0 + lr) * RSTR + lk);

    float acc[4][4];
#pragma unroll
    for (int i = 0; i < 4; i++) acc[i][0] = acc[i][1] = acc[i][2] = acc[i][3] = 0.f;

    float4 xv[4];

#define G1_BLOAD(st_, c_) do {                                                \
    const uint32_t d = dB + (st_) * G1_STG;                                   \
    cpa16(d + bj * 16,        bth + (c_) * 64 + bj * 8);                      \
    cpa16(d + (bj + 4) * 16,  bth + (c_) * 64 + (bj + 4) * 8);                \
} while (0)

#define G1_XLDG(c_) do {                                                      \
    const float* srcx = xrp + (c_) * 64;                                      \
    _Pragma("unroll")                                                         \
    for (int seg = 0; seg < 4; seg++)                                         \
        xv[seg] = *(const float4*)(srcx + seg * 16 + lq * 4);                 \
} while (0)

#define G1_XSTS(st_) do {                                                     \
    char* ah = sm + (st_) * G1_STG + lrow * RSTR + lq * 8;                    \
    _Pragma("unroll")                                                         \
    for (int seg = 0; seg < 4; seg++) {                                       \
        uint32_t h01, h23, l01, l23;                                          \
        split2h(xv[seg].x, xv[seg].y, h01, l01);                              \
        split2h(xv[seg].z, xv[seg].w, h23, l23);                              \
        *(uint2*)(ah + seg * 32)        = make_uint2(h01, h23);               \
        *(uint2*)(ah + 9216 + seg * 32) = make_uint2(l01, l23);               \
    }                                                                         \
} while (0)

    // prologue: chunk 0 -> stage 0
    G1_BLOAD(0, 0);
    CP_COMMIT();
    G1_XLDG(0);
    G1_XSTS(0);

    for (int c = 0; c < 32; c++) {
        const int s = c & 1;
        CP_WAIT0();
        __syncthreads();
        if (c < 31) {
            G1_BLOAD(s ^ 1, c + 1);
            CP_COMMIT();
            G1_XLDG(c + 1);          // LDG in flight during compute below
        }
        // compute chunk c from stage s
        const uint32_t st = sb + s * G1_STG;
#pragma unroll
        for (int ks = 0; ks < 4; ks++) {
            const uint32_t ka = ks * 32;
            uint32_t Ah[4], Al[4], B0[4], B1[4];
            ldsm4(Ah, st + offA + ka);
            ldsm4(B0, st + 18432 + offB + ka);
            ldsm4(B1, st + 18432 + 16 * RSTR + offB + ka);
            ldsm4(Al, st + 9216 + offA + ka);
            // xh * B
            mma16816h(acc[0], Ah[0], Ah[1], Ah[2], Ah[3], B0[0], B0[2]);
            mma16816h(acc[1], Ah[0], Ah[1], Ah[2], Ah[3], B0[1], B0[3]);
            mma16816h(acc[2], Ah[0], Ah[1], Ah[2], Ah[3], B1[0], B1[2]);
            mma16816h(acc[3], Ah[0], Ah[1], Ah[2], Ah[3], B1[1], B1[3]);
            // xl * B
            mma16816h(acc[0], Al[0], Al[1], Al[2], Al[3], B0[0], B0[2]);
            mma16816h(acc[1], Al[0], Al[1], Al[2], Al[3], B0[1], B0[3]);
            mma16816h(acc[2], Al[0], Al[1], Al[2], Al[3], B1[0], B1[2]);
            mma16816h(acc[3], Al[0], Al[1], Al[2], Al[3], B1[1], B1[3]);
        }
        if (c < 31) G1_XSTS(s ^ 1);   // split + store AFTER compute (LDG hidden)
    }

    // store partials (deterministic plain stores)
    float* vp = g_vpart[ksl];
    const size_t r0 = (size_t)(t + 8 * (g * 64 + m0 + gr));
    const size_t r1 = r0 + 64;   // row + 8 in tile = +64 global
#pragma unroll
    for (int nt = 0; nt < 4; nt++) {
        const int col = n0 + nt * 8 + 2 * p;
        *(float2*)&vp[r0 * 64 + col] = make_float2(acc[nt][0], acc[nt][1]);
        *(float2*)&vp[r1 * 64 + col] = make_float2(acc[nt][2], acc[nt][3]);
    }
}

// ---------------------------------------------------------------------------
// k_vred: v = sum of 2 partials, split to fp16 hi/lo.  512 blocks x 256 thr.
// ---------------------------------------------------------------------------
__global__ __launch_bounds__(256) void k_vred() {
    const int idx = blockIdx.x * 256 + threadIdx.x;   // float4 index
    const float4* p0 = (const float4*)g_vpart[0];
    const float4* p1 = (const float4*)g_vpart[1];
    float4 a = p0[idx], b = p1[idx];
    float4 s = make_float4(a.x + b.x, a.y + b.y, a.z + b.z, a.w + b.w);
    uint32_t h01, l01, h23, l23;
    split2h(s.x, s.y, h01, l01);
    split2h(s.z, s.w, h23, l23);
    *(uint2*)&g_vhi[(size_t)idx * 4] = make_uint2(h01, h23);
    *(uint2*)&g_vlo[(size_t)idx * 4] = make_uint2(l01, l23);
}

// ---------------------------------------------------------------------------
// k_gemm2: y = v @ och^T (fp16 2-term: vh*oc + vl*oc).  Tile 128x128, K=64,
// warp tile 64x32.  smem: AH@0 AL@18432 BH@36864 = 55296B.  grid (32, 64).
// ---------------------------------------------------------------------------
#define G2_SMEM 55296

__global__ __launch_bounds__(256, 2) void k_gemm2(float* __restrict__ y) {
    extern __shared__ char sm[];
    const uint32_t sb = smem_u32(sm);
    const int tid = threadIdx.x, warp = tid >> 5, lane = tid & 31;
    const int gr = lane >> 2, p = lane & 3;
    const int n0b = blockIdx.x * 128, m0b = blockIdx.y * 128;

    {   // cp.async all 3 tiles
        const int row = tid >> 1, q = (tid & 1) * 4;
        const uint32_t drow = sb + row * RSTR;
        const __half* sa  = g_vhi + (size_t)(m0b + row) * 64;
        const __half* sal = g_vlo + (size_t)(m0b + row) * 64;
        const __half* sbh = g_och + (size_t)(n0b + row) * 64;
#pragma unroll
        for (int j = 0; j < 4; j++) {
            cpa16(drow + (q + j) * 16,         sa  + (q + j) * 8);
            cpa16(drow + 18432 + (q + j) * 16, sal + (q + j) * 8);
            cpa16(drow + 36864 + (q + j) * 16, sbh + (q + j) * 8);
        }
    }
    CP_COMMIT();
    CP_WAIT0();
    __syncthreads();

    const int m0 = (warp >> 2) * 64, n0 = (warp & 3) * 32;
    const int lr = (lane & 7) + ((lane >> 3) & 1) * 8;
    const int lk = (lane >> 4) * 16;
    const uint32_t offA = (uint32_t)((m0 + lr) * RSTR + lk);
    const uint32_t offB = (uint32_t)((n0 + lr) * RSTR + lk);

    float acc[4][4][4];
#pragma unroll
    for (int mt = 0; mt < 4; mt++)
#pragma unroll
        for (int nt = 0; nt < 4; nt++)
            acc[mt][nt][0] = acc[mt][nt][1] = acc[mt][nt][2] = acc[mt][nt][3] = 0.f;

#pragma unroll
    for (int ks = 0; ks < 4; ks++) {
        const uint32_t ka = ks * 32;
        uint32_t Ah[4][4], Al[4][4], B0[4], B1[4];
#pragma unroll
        for (int mt = 0; mt < 4; mt++)
            ldsm4(Ah[mt], sb + offA + mt * 16 * RSTR + ka);
        ldsm4(B0, sb + 36864 + offB + ka);
        ldsm4(B1, sb + 36864 + 16 * RSTR + offB + ka);
        // vh * oc
#pragma unroll
        for (int mt = 0; mt < 4; mt++) {
            mma16816h(acc[mt][0], Ah[mt][0], Ah[mt][1], Ah[mt][2], Ah[mt][3], B0[0], B0[2]);
            mma16816h(acc[mt][1], Ah[mt][0], Ah[mt][1], Ah[mt][2], Ah[mt][3], B0[1], B0[3]);
            mma16816h(acc[mt][2], Ah[mt][0], Ah[mt][1], Ah[mt][2], Ah[mt][3], B1[0], B1[2]);
            mma16816h(acc[mt][3], Ah[mt][0], Ah[mt][1], Ah[mt][2], Ah[mt][3], B1[1], B1[3]);
        }
        // vl * oc
#pragma unroll
        for (int mt = 0; mt < 4; mt++)
            ldsm4(Al[mt], sb + 18432 + offA + mt * 16 * RSTR + ka);
#pragma unroll
        for (int mt = 0; mt < 4; mt++) {
            mma16816h(acc[mt][0], Al[mt][0], Al[mt][1], Al[mt][2], Al[mt][3], B0[0], B0[2]);
            mma16816h(acc[mt][1], Al[mt][0], Al[mt][1], Al[mt][2], Al[mt][3], B0[1], B0[3]);
            mma16816h(acc[mt][2], Al[mt][0], Al[mt][1], Al[mt][2], Al[mt][3], B1[0], B1[2]);
            mma16816h(acc[mt][3], Al[mt][0], Al[mt][1], Al[mt][2], Al[mt][3], B1[1], B1[3]);
        }
    }

#pragma unroll
    for (int mt = 0; mt < 4; mt++) {
#pragma unroll
        for (int nt = 0; nt < 4; nt++) {
            const int row = m0b + m0 + mt * 16 + gr;
            const int col = n0b + n0 + nt * 8 + 2 * p;
            *(float2*)&y[(size_t)row * OUT_ + col] =
                make_float2(acc[mt][nt][0], acc[mt][nt][1]);
            *(float2*)&y[(size_t)(row + 8) * OUT_ + col] =
                make_float2(acc[mt][nt][2], acc[mt][nt][3]);
        }
    }
}

// ---------------------------------------------------------------------------
extern "C" void kernel_launch(void* const* d_in, const int* in_sizes, int n_in,
                              void* d_out, int out_size) {
    const float* x        = (const float*)d_in[0];
    const float* tc       = (const float*)d_in[1];
    const float* task     = (const float*)d_in[2];
    const float* in_core  = (const float*)d_in[3];
    const float* out_core = (const float*)d_in[4];
    float* y = (float*)d_out;

    cudaFuncSetAttribute(k_gemm1, cudaFuncAttributeMaxDynamicSharedMemorySize, G1_SMEM);
    cudaFuncSetAttribute(k_gemm2, cudaFuncAttributeMaxDynamicSharedMemorySize, G2_SMEM);

    k_pre1<<<192, 256>>>(task, tc, out_core);
    k_bt<<<128, 256>>>(in_core);
    k_gemm1<<<256, 256, G1_SMEM>>>(x);
    k_vred<<<512, 256>>>();
    k_gemm2<<<dim3(OUT_ / 128, BT_ / 128), 256, G2_SMEM>>>(y);
}

// round 11
// speedup vs baseline: 1.9443x; 1.1405x over previous
#include <cuda_runtime.h>
#include <cuda_bf16.h>
#include <cuda_fp16.h>
#include <cstdint>

#define BT_   8192
#define IN_   4096
#define OUT_  4096
#define R_    64
#define T_    8

// ---------------- device scratch ----------------
__device__ float          g_W1[T_ * R_ * R_];
__device__ __half         g_Bth[T_ * R_ * IN_];    // Bt = in_core@W1 : fp16 [t][n][k]
__device__ __half         g_och[OUT_ * R_];        // out_core fp16 [n][k]
__device__ float          g_vpart[2][BT_ * R_];    // split-K partials of v
__device__ __half         g_vhi[BT_ * R_];         // v fp16

typedef unsigned long long u64;

// ---------- packed f32x2 ----------
__device__ __forceinline__ u64 pk2(float lo, float hi) {
    u64 r; asm("mov.b64 %0, {%1, %2};" : "=l"(r) : "f"(lo), "f"(hi)); return r;
}
__device__ __forceinline__ void upk2(u64 v, float& lo, float& hi) {
    asm("mov.b64 {%0, %1}, %2;" : "=f"(lo), "=f"(hi) : "l"(v));
}
__device__ __forceinline__ u64 ffma2(u64 a, u64 b, u64 c) {
    u64 d; asm("fma.rn.f32x2 %0, %1, %2, %3;" : "=l"(d) : "l"(a), "l"(b), "l"(c)); return d;
}

// ---------- tensor-core primitives (base-ISA, sm_103-safe) ----------
__device__ __forceinline__ void mma16816h(float* c, uint32_t a0, uint32_t a1,
                                          uint32_t a2, uint32_t a3,
                                          uint32_t b0, uint32_t b1) {
    asm volatile(
        "mma.sync.aligned.m16n8k16.row.col.f32.f16.f16.f32 "
        "{%0,%1,%2,%3}, {%4,%5,%6,%7}, {%8,%9}, {%0,%1,%2,%3};"
        : "+f"(c[0]), "+f"(c[1]), "+f"(c[2]), "+f"(c[3])
        : "r"(a0), "r"(a1), "r"(a2), "r"(a3), "r"(b0), "r"(b1));
}
__device__ __forceinline__ void ldsm4(uint32_t* r, uint32_t saddr) {
    asm volatile("ldmatrix.sync.aligned.m8n8.x4.shared.b16 {%0,%1,%2,%3}, [%4];"
                 : "=r"(r[0]), "=r"(r[1]), "=r"(r[2]), "=r"(r[3]) : "r"(saddr));
}
__device__ __forceinline__ void cpa16(uint32_t dst, const void* src) {
    asm volatile("cp.async.cg.shared.global [%0], [%1], 16;" :: "r"(dst), "l"(src));
}
#define CP_COMMIT() asm volatile("cp.async.commit_group;" ::: "memory")
#define CP_WAIT0()  asm volatile("cp.async.wait_group 0;" ::: "memory")

__device__ __forceinline__ uint32_t smem_u32(const void* p) {
    uint32_t a;
    asm("{ .reg .u64 t; cvta.to.shared.u64 t, %1; cvt.u32.u64 %0, t; }" : "=r"(a) : "l"(p));
    return a;
}

// row stride in all smem tile matrices: 144 bytes (36 words) -> LDSM conflict-free
#define RSTR 144

// ---------------------------------------------------------------------------
// k_pre1: out_core fp16 (bx<64) + W1 (bx in [64,192)).
// ---------------------------------------------------------------------------
__global__ __launch_bounds__(256) void k_pre1(const float* __restrict__ task,
                                              const float* __restrict__ tc,
                                              const float* __restrict__ out_core) {
    const int bx = blockIdx.x, tid = threadIdx.x;
    if (bx < 64) {
        const size_t base = (size_t)bx * 4096 + (size_t)tid * 16;
#pragma unroll
        for (int j = 0; j < 16; j += 4) {
            float4 v = *(const float4*)&out_core[base + j];
            __half2 h0 = __floats2half2_rn(v.x, v.y);
            __half2 h1 = __floats2half2_rn(v.z, v.w);
            *(uint32_t*)&g_och[base + j]     = *(uint32_t*)&h0;
            *(uint32_t*)&g_och[base + j + 2] = *(uint32_t*)&h1;
        }
    } else {
        const int idx = (bx - 64) * 256 + tid;
        const int t = idx >> 12, kl = idx & 4095;
        float a0 = 0, a1 = 0, a2 = 0, a3 = 0;
#pragma unroll
        for (int j = 0; j < 64; j += 4) {
            a0 += task[t * 64 + j + 0] * tc[(size_t)(j + 0) * 4096 + kl];
            a1 += task[t * 64 + j + 1] * tc[(size_t)(j + 1) * 4096 + kl];
            a2 += task[t * 64 + j + 2] * tc[(size_t)(j + 2) * 4096 + kl];
            a3 += task[t * 64 + j + 3] * tc[(size_t)(j + 3) * 4096 + kl];
        }
        g_W1[idx] = (a0 + a1) + (a2 + a3);
    }
}

// ---------------------------------------------------------------------------
// k_bt: Bt[t][k][n] = sum_j in_core[k][j]*W1[t][j][n] -> fp16 [t][n][k].
// ---------------------------------------------------------------------------
__global__ __launch_bounds__(256) void k_bt(const float* __restrict__ in_core) {
    __shared__ float W1s[4096];
    const int bx = blockIdx.x, tid = threadIdx.x;
    const int t = bx >> 4;
    const int row = (bx & 15) * 256 + tid;      // k index
    {
        const float4* src = (const float4*)(g_W1 + t * 4096);
        float4* dst = (float4*)W1s;
#pragma unroll
        for (int i = 0; i < 4; i++) dst[tid + i * 256] = src[tid + i * 256];
    }
    __syncthreads();

    u64 acc[32];
#pragma unroll
    for (int i = 0; i < 32; i++) acc[i] = 0ull;

    const float* icr = in_core + (size_t)row * 64;
#pragma unroll
    for (int jc = 0; jc < 4; jc++) {
        float4 a4[4];
#pragma unroll
        for (int q = 0; q < 4; q++) a4[q] = *(const float4*)(icr + jc * 16 + q * 4);
#pragma unroll
        for (int jj = 0; jj < 16; jj++) {
            const int j = jc * 16 + jj;
            float a = ((const float*)a4)[jj];
            u64 a2 = pk2(a, a);
#pragma unroll
            for (int i2 = 0; i2 < 16; i2++) {
                ulonglong2 w = *(const ulonglong2*)&W1s[j * 64 + i2 * 4];
                acc[2 * i2]     = ffma2(a2, w.x, acc[2 * i2]);
                acc[2 * i2 + 1] = ffma2(a2, w.y, acc[2 * i2 + 1]);
            }
        }
    }
    // fp16 round + transposed store: Bt[t][n][row]
#pragma unroll
    for (int i = 0; i < 32; i++) {
        float v0, v1;
        upk2(acc[i], v0, v1);
        const size_t b0 = ((size_t)t * 64 + 2 * i) * IN_ + row;
        const size_t b1 = ((size_t)t * 64 + 2 * i + 1) * IN_ + row;
        g_Bth[b0] = __float2half(v0);
        g_Bth[b1] = __float2half(v1);
    }
}

// ---------------------------------------------------------------------------
// k_gemm1: v_partial = x @ Bt[t]  (tile 64m x 64n, K-slice 2048 = 32 chunks
// of 64). 256 CTAs: mtile = bx>>1 (t = mtile&7, g = mtile>>3), kslice = bx&1.
// fp16 single-term: x_fp16 @ Bt_fp16.  Pipelined as in R9/R10.
// smem/stage 18432B: AH@0 BH@9216;  2 stages = 36864B.
// ---------------------------------------------------------------------------
#define G1_STG  18432
#define G1_SMEM 36864

__global__ __launch_bounds__(256, 2) void k_gemm1(const float* __restrict__ x) {
    extern __shared__ char sm[];
    const uint32_t sb = smem_u32(sm);
    const int tid = threadIdx.x, warp = tid >> 5, lane = tid & 31;
    const int gr = lane >> 2, p = lane & 3;
    const int bx = blockIdx.x;
    const int mtile = bx >> 1, ksl = bx & 1;
    const int t = mtile & 7, g = mtile >> 3;
    const int koff = ksl * 2048;

    // x loader mapping: 4 threads per row
    const int lrow = tid >> 2, lq = tid & 3;
    const float* xrp = x + (size_t)(t + 8 * (g * 64 + lrow)) * IN_ + koff;

    // B cp.async mapping
    const int bn = tid >> 2, bj = tid & 3;
    const __half* bth = g_Bth + ((size_t)t * 64 + bn) * IN_ + koff;
    const uint32_t dB = sb + 9216 + bn * RSTR;

    // ldmatrix lane roles
    const int m0 = (warp >> 1) * 16, n0 = (warp & 1) * 32;
    const int lr = (lane & 7) + ((lane >> 3) & 1) * 8;
    const int lk = (lane >> 4) * 16;
    const uint32_t offA = (uint32_t)((m0 + lr) * RSTR + lk);
    const uint32_t offB = (uint32_t)((n0 + lr) * RSTR + lk);

    float acc[4][4];
#pragma unroll
    for (int i = 0; i < 4; i++) acc[i][0] = acc[i][1] = acc[i][2] = acc[i][3] = 0.f;

    float4 xv[4];

#define G1_BLOAD(st_, c_) do {                                                \
    const uint32_t d = dB + (st_) * G1_STG;                                   \
    cpa16(d + bj * 16,        bth + (c_) * 64 + bj * 8);                      \
    cpa16(d + (bj + 4) * 16,  bth + (c_) * 64 + (bj + 4) * 8);                \
} while (0)

#define G1_XLDG(c_) do {                                                      \
    const float* srcx = xrp + (c_) * 64;                                      \
    _Pragma("unroll")                                                         \
    for (int seg = 0; seg < 4; seg++)                                         \
        xv[seg] = *(const float4*)(srcx + seg * 16 + lq * 4);                 \
} while (0)

#define G1_XSTS(st_) do {                                                     \
    char* ah = sm + (st_) * G1_STG + lrow * RSTR + lq * 8;                    \
    _Pragma("unroll")                                                         \
    for (int seg = 0; seg < 4; seg++) {                                       \
        __half2 h0 = __floats2half2_rn(xv[seg].x, xv[seg].y);                 \
        __half2 h1 = __floats2half2_rn(xv[seg].z, xv[seg].w);                 \
        *(uint2*)(ah + seg * 32) = make_uint2(*(uint32_t*)&h0, *(uint32_t*)&h1); \
    }                                                                         \
} while (0)

    // prologue: chunk 0 -> stage 0
    G1_BLOAD(0, 0);
    CP_COMMIT();
    G1_XLDG(0);
    G1_XSTS(0);

    for (int c = 0; c < 32; c++) {
        const int s = c & 1;
        CP_WAIT0();
        __syncthreads();
        if (c < 31) {
            G1_BLOAD(s ^ 1, c + 1);
            CP_COMMIT();
            G1_XLDG(c + 1);          // LDG in flight during compute below
        }
        // compute chunk c from stage s
        const uint32_t st = sb + s * G1_STG;
#pragma unroll
        for (int ks = 0; ks < 4; ks++) {
            const uint32_t ka = ks * 32;
            uint32_t Ah[4], B0[4], B1[4];
            ldsm4(Ah, st + offA + ka);
            ldsm4(B0, st + 9216 + offB + ka);
            ldsm4(B1, st + 9216 + 16 * RSTR + offB + ka);
            mma16816h(acc[0], Ah[0], Ah[1], Ah[2], Ah[3], B0[0], B0[2]);
            mma16816h(acc[1], Ah[0], Ah[1], Ah[2], Ah[3], B0[1], B0[3]);
            mma16816h(acc[2], Ah[0], Ah[1], Ah[2], Ah[3], B1[0], B1[2]);
            mma16816h(acc[3], Ah[0], Ah[1], Ah[2], Ah[3], B1[1], B1[3]);
        }
        if (c < 31) G1_XSTS(s ^ 1);   // cvt + store AFTER compute (LDG hidden)
    }

    // store partials (deterministic plain stores)
    float* vp = g_vpart[ksl];
    const size_t r0 = (size_t)(t + 8 * (g * 64 + m0 + gr));
    const size_t r1 = r0 + 64;   // row + 8 in tile = +64 global
#pragma unroll
    for (int nt = 0; nt < 4; nt++) {
        const int col = n0 + nt * 8 + 2 * p;
        *(float2*)&vp[r0 * 64 + col] = make_float2(acc[nt][0], acc[nt][1]);
        *(float2*)&vp[r1 * 64 + col] = make_float2(acc[nt][2], acc[nt][3]);
    }
}

// ---------------------------------------------------------------------------
// k_vred: v = sum of 2 partials -> fp16.  512 blocks x 256 thr.
// ---------------------------------------------------------------------------
__global__ __launch_bounds__(256) void k_vred() {
    const int idx = blockIdx.x * 256 + threadIdx.x;   // float4 index
    const float4* p0 = (const float4*)g_vpart[0];
    const float4* p1 = (const float4*)g_vpart[1];
    float4 a = p0[idx], b = p1[idx];
    __half2 h0 = __floats2half2_rn(a.x + b.x, a.y + b.y);
    __half2 h1 = __floats2half2_rn(a.z + b.z, a.w + b.w);
    *(uint2*)&g_vhi[(size_t)idx * 4] = make_uint2(*(uint32_t*)&h0, *(uint32_t*)&h1);
}

// ---------------------------------------------------------------------------
// k_gemm2: y = v @ och^T (fp16 single-term).  Tile 128x128, K=64,
// warp tile 64x32.  smem: AH@0 BH@18432 = 36864B.  grid (32, 64).
// ---------------------------------------------------------------------------
#define G2_SMEM 36864

__global__ __launch_bounds__(256, 2) void k_gemm2(float* __restrict__ y) {
    extern __shared__ char sm[];
    const uint32_t sb = smem_u32(sm);
    const int tid = threadIdx.x, warp = tid >> 5, lane = tid & 31;
    const int gr = lane >> 2, p = lane & 3;
    const int n0b = blockIdx.x * 128, m0b = blockIdx.y * 128;

    {   // cp.async both tiles
        const int row = tid >> 1, q = (tid & 1) * 4;
        const uint32_t drow = sb + row * RSTR;
        const __half* sa  = g_vhi + (size_t)(m0b + row) * 64;
        const __half* sbh = g_och + (size_t)(n0b + row) * 64;
#pragma unroll
        for (int j = 0; j < 4; j++) {
            cpa16(drow + (q + j) * 16,         sa  + (q + j) * 8);
            cpa16(drow + 18432 + (q + j) * 16, sbh + (q + j) * 8);
        }
    }
    CP_COMMIT();
    CP_WAIT0();
    __syncthreads();

    const int m0 = (warp >> 2) * 64, n0 = (warp & 3) * 32;
    const int lr = (lane & 7) + ((lane >> 3) & 1) * 8;
    const int lk = (lane >> 4) * 16;
    const uint32_t offA = (uint32_t)((m0 + lr) * RSTR + lk);
    const uint32_t offB = (uint32_t)((n0 + lr) * RSTR + lk);

    float acc[4][4][4];
#pragma unroll
    for (int mt = 0; mt < 4; mt++)
#pragma unroll
        for (int nt = 0; nt < 4; nt++)
            acc[mt][nt][0] = acc[mt][nt][1] = acc[mt][nt][2] = acc[mt][nt][3] = 0.f;

#pragma unroll
    for (int ks = 0; ks < 4; ks++) {
        const uint32_t ka = ks * 32;
        uint32_t Ah[4][4], B0[4], B1[4];
#pragma unroll
        for (int mt = 0; mt < 4; mt++)
            ldsm4(Ah[mt], sb + offA + mt * 16 * RSTR + ka);
        ldsm4(B0, sb + 18432 + offB + ka);
        ldsm4(B1, sb + 18432 + 16 * RSTR + offB + ka);
#pragma unroll
        for (int mt = 0; mt < 4; mt++) {
            mma16816h(acc[mt][0], Ah[mt][0], Ah[mt][1], Ah[mt][2], Ah[mt][3], B0[0], B0[2]);
            mma16816h(acc[mt][1], Ah[mt][0], Ah[mt][1], Ah[mt][2], Ah[mt][3], B0[1], B0[3]);
            mma16816h(acc[mt][2], Ah[mt][0], Ah[mt][1], Ah[mt][2], Ah[mt][3], B1[0], B1[2]);
            mma16816h(acc[mt][3], Ah[mt][0], Ah[mt][1], Ah[mt][2], Ah[mt][3], B1[1], B1[3]);
        }
    }

#pragma unroll
    for (int mt = 0; mt < 4; mt++) {
#pragma unroll
        for (int nt = 0; nt < 4; nt++) {
            const int row = m0b + m0 + mt * 16 + gr;
            const int col = n0b + n0 + nt * 8 + 2 * p;
            *(float2*)&y[(size_t)row * OUT_ + col] =
                make_float2(acc[mt][nt][0], acc[mt][nt][1]);
            *(float2*)&y[(size_t)(row + 8) * OUT_ + col] =
                make_float2(acc[mt][nt][2], acc[mt][nt][3]);
        }
    }
}

// ---------------------------------------------------------------------------
extern "C" void kernel_launch(void* const* d_in, const int* in_sizes, int n_in,
                              void* d_out, int out_size) {
    const float* x        = (const float*)d_in[0];
    const float* tc       = (const float*)d_in[1];
    const float* task     = (const float*)d_in[2];
    const float* in_core  = (const float*)d_in[3];
    const float* out_core = (const float*)d_in[4];
    float* y = (float*)d_out;

    cudaFuncSetAttribute(k_gemm1, cudaFuncAttributeMaxDynamicSharedMemorySize, G1_SMEM);
    cudaFuncSetAttribute(k_gemm2, cudaFuncAttributeMaxDynamicSharedMemorySize, G2_SMEM);

    k_pre1<<<192, 256>>>(task, tc, out_core);
    k_bt<<<128, 256>>>(in_core);
    k_gemm1<<<256, 256, G1_SMEM>>>(x);
    k_vred<<<512, 256>>>();
    k_gemm2<<<dim3(OUT_ / 128, BT_ / 128), 256, G2_SMEM>>>(y);
}